// round 10
// baseline (speedup 1.0000x reference)
#include <cuda_runtime.h>

#define HID 8192
#define BATCH 512
#define NIN 16
#define RANK 8
#define NOUT 4
#define GRID 256
#define TPB 256

// u partials: two H-halves, folded in phase 2 (fixed order => deterministic)
__device__ float g_u_part[2][BATCH * RANK];
// per-j-tile readout partials, folded in phase 3 (fixed order => deterministic)
__device__ float g_out_part[32][BATCH * NOUT];
__device__ unsigned int g_bar;   // monotone ticket counter, never reset (replay-safe)

typedef unsigned long long ull;

__device__ __forceinline__ void ffma2(ull& d, ull a, ull b) {
    asm("fma.rn.f32x2 %0, %1, %2, %0;" : "+l"(d) : "l"(a), "l"(b));
}
__device__ __forceinline__ void unpack2(float& lo, float& hi, ull v) {
    asm("mov.b64 {%0, %1}, %2;" : "=f"(lo), "=f"(hi) : "l"(v));
}

__device__ __forceinline__ void grid_barrier() {
    __syncthreads();
    if (threadIdx.x == 0) {
        __threadfence();
        unsigned int old = atomicAdd(&g_bar, 1u);
        unsigned int target = (old / GRID + 1u) * GRID;
        while ((int)(*(volatile unsigned int*)&g_bar - target) < 0)
            __nanosleep(32);
        __threadfence();
    }
    __syncthreads();
}

__global__ void __launch_bounds__(TPB, 2) k_fused(const float* __restrict__ input,
                                                  const float* __restrict__ hidden,
                                                  const float* __restrict__ Win,
                                                  const float* __restrict__ L,
                                                  const float* __restrict__ R,
                                                  const float* __restrict__ Wout,
                                                  float* __restrict__ nh,
                                                  float* __restrict__ out) {
    const int t = threadIdx.x;
    const int lane = t & 31, w = t >> 5;

    __shared__ float red[8][32];
    __shared__ __align__(16) float comb[64][24];     // phase 2: [input(16) | u(8)]
    __shared__ __align__(16) float th_s[32][260];    // phase 2: tanh(nh) half-tile
    __shared__ __align__(16) float wout_s[4][256];   // phase 2: Wout tile

    // ===================== Phase 1: u partials (R7-proven) ================
    {
        const int bg = blockIdx.x >> 1;          // 0..127 -> 4 batch rows
        const int half = blockIdx.x & 1;         // H-half
        const int bbase = bg * 4;

        float acc[32];
#pragma unroll
        for (int i = 0; i < 32; i++) acc[i] = 0.0f;

#pragma unroll
        for (int it = 0; it < 4; it++) {
            const int j = half * 4096 + it * 1024 + t * 4;
            float4 h4[4];
#pragma unroll
            for (int bl = 0; bl < 4; bl++)
                h4[bl] = *(const float4*)(hidden + (bbase + bl) * HID + j);
            float th[4][4];
#pragma unroll
            for (int bl = 0; bl < 4; bl++) {
                th[bl][0] = __tanhf(h4[bl].x);
                th[bl][1] = __tanhf(h4[bl].y);
                th[bl][2] = __tanhf(h4[bl].z);
                th[bl][3] = __tanhf(h4[bl].w);
            }
#pragma unroll
            for (int r = 0; r < 8; r++) {
                float4 rv = *(const float4*)(R + r * HID + j);
#pragma unroll
                for (int bl = 0; bl < 4; bl++) {
                    float a = acc[bl * 8 + r];
                    a = fmaf(th[bl][0], rv.x, a);
                    a = fmaf(th[bl][1], rv.y, a);
                    a = fmaf(th[bl][2], rv.z, a);
                    a = fmaf(th[bl][3], rv.w, a);
                    acc[bl * 8 + r] = a;
                }
            }
        }

        // fold 32 values across lanes: 31 SHFL, lane L ends with total of acc[L]
#pragma unroll
        for (int m = 16; m >= 1; m >>= 1) {
            const bool up = (lane & m) != 0;
#pragma unroll
            for (int i = 0; i < m; i++) {
                float send = up ? acc[i] : acc[i + m];
                float got = __shfl_xor_sync(0xffffffffu, send, m);
                acc[i] = (up ? acc[i + m] : acc[i]) + got;
            }
        }
        red[w][lane] = acc[0];
        __syncthreads();
        if (t < 32) {
            float s = 0.0f;
#pragma unroll
            for (int w2 = 0; w2 < 8; w2++) s += red[w2][t];
            g_u_part[half][bbase * RANK + t] = s;   // L -> (bbase + L>>3)*8 + (L&7)
        }
    }

    grid_barrier();

    // ============ Phase 2: new_h + smem-staged fused readout ==============
    {
        const int jt = blockIdx.x & 31;          // 32 j-tiles of 256
        const int bc = blockIdx.x >> 5;          // 8 batch chunks of 64
        const int b0 = bc * 64;
        const int jg = t & 127;                  // 128 groups of 2 j
        const int bs = t >> 7;                   // 0..1
        const int j0 = jt * 256 + jg * 2;

        // stage [input | u] per batch row: comb[bi][0..15]=input, [16..23]=u
        for (int v = t; v < 64 * 24; v += TPB) {
            const int bi = v / 24, c = v - bi * 24;
            float val;
            if (c < NIN) {
                val = input[(b0 + bi) * NIN + c];
            } else {
                const int idx = (b0 + bi) * RANK + (c - NIN);
                val = (g_u_part[0][idx] + g_u_part[1][idx]) * (1.0f / (float)HID);
            }
            comb[bi][c] = val;
        }
        // stage Wout tile: wout_s[o][jj] for this block's 256 j
        for (int v = t; v < 4 * 256; v += TPB)
            wout_s[v >> 8][v & 255] = Wout[(v >> 8) * HID + jt * 256 + (v & 255)];

        ull wj[2][8];
        ull lj[2][4];
#pragma unroll
        for (int jj = 0; jj < 2; jj++) {
            const ull* wr = (const ull*)(Win + (j0 + jj) * NIN);
#pragma unroll
            for (int i = 0; i < 8; i++) wj[jj][i] = wr[i];
            const ull* lr = (const ull*)(L + (j0 + jj) * RANK);
#pragma unroll
            for (int r = 0; r < 4; r++) lj[jj][r] = lr[r];
        }
        __syncthreads();

#pragma unroll
        for (int half = 0; half < 2; half++) {
#pragma unroll 4
            for (int bi = half * 32 + bs; bi < half * 32 + 32; bi += 2) {
                const int b = b0 + bi;

                // 6x LDS.128 broadcast: 24 floats = 12 f32x2 operand pairs
                union { float4 f4[6]; ull p[12]; } cb;
                const float4* cp = (const float4*)&comb[bi][0];
#pragma unroll
                for (int q = 0; q < 6; q++) cb.f4[q] = cp[q];

                float2 h2 = *(const float2*)(hidden + b * HID + j0);

                float res[2];
#pragma unroll
                for (int jj = 0; jj < 2; jj++) {
                    ull acc = 0ULL;
#pragma unroll
                    for (int i = 0; i < 8; i++) ffma2(acc, wj[jj][i], cb.p[i]);
#pragma unroll
                    for (int r = 0; r < 4; r++) ffma2(acc, lj[jj][r], cb.p[8 + r]);
                    float lo, hi;
                    unpack2(lo, hi, acc);
                    res[jj] = lo + hi;
                }

                float2 o2;
                o2.x = fmaf(0.1f, res[0], 0.9f * h2.x);
                o2.y = fmaf(0.1f, res[1], 0.9f * h2.y);
                *(float2*)(nh + b * HID + j0) = o2;

                // stage tanh(nh) for the block readout (no shuffles here)
                float2 tpair;
                tpair.x = __tanhf(o2.x);
                tpair.y = __tanhf(o2.y);
                *(float2*)&th_s[bi - half * 32][jg * 2] = tpair;
            }
            __syncthreads();

            // block GEMV: 128 (b,o) pairs x 2 j-halves of 128
            {
                const int pr = t >> 1, jh = t & 1;
                const int bl = pr >> 2, o = pr & 3;
                const float4* tp = (const float4*)&th_s[bl][jh * 128];
                const float4* wp = (const float4*)&wout_s[o][jh * 128];
                float s = 0.0f;
#pragma unroll
                for (int i = 0; i < 32; i++) {
                    float4 a = tp[i];
                    float4 bb = wp[i];
                    s = fmaf(a.x, bb.x, s);
                    s = fmaf(a.y, bb.y, s);
                    s = fmaf(a.z, bb.z, s);
                    s = fmaf(a.w, bb.w, s);
                }
                s += __shfl_xor_sync(0xffffffffu, s, 1);
                if (jh == 0)
                    g_out_part[jt][(b0 + half * 32 + bl) * NOUT + o] = s;
            }
            __syncthreads();
        }
    }

    grid_barrier();

    // ============ Phase 3: distributed tiny fold ==========================
    {
        // block handles 8 outputs; each output: 32 lanes read 32 partials
        const int oi = t >> 5;                   // 0..7
        const int idx = blockIdx.x * 8 + oi;     // 256*8 = 2048 = BATCH*NOUT
        float s = g_out_part[lane][idx];
#pragma unroll
        for (int off = 16; off > 0; off >>= 1)
            s += __shfl_xor_sync(0xffffffffu, s, off);
        if (lane == 0) out[idx] = s * (1.0f / (float)HID);
    }
}

extern "C" void kernel_launch(void* const* d_in, const int* in_sizes, int n_in,
                              void* d_out, int out_size) {
    const float* input  = (const float*)d_in[0];  // [512,16]
    const float* hidden = (const float*)d_in[1];  // [512,8192]
    const float* Win    = (const float*)d_in[2];  // [8192,16]
    const float* L      = (const float*)d_in[3];  // [8192,8]
    const float* R      = (const float*)d_in[4];  // [8,8192]
    const float* Wout   = (const float*)d_in[5];  // [4,8192]

    float* out = (float*)d_out;                   // [512,4] then [512,8192]
    float* nh  = out + BATCH * NOUT;

    k_fused<<<GRID, TPB>>>(input, hidden, Win, L, R, Wout, nh, out);
}

// round 11
// speedup vs baseline: 1.7766x; 1.7766x over previous
#include <cuda_runtime.h>

#define HID 8192
#define BATCH 512
#define NIN 16
#define RANK 8
#define NOUT 4
#define GRID 256
#define TPB 512

// u partials: two H-halves, folded in phase 2 (fixed order => deterministic)
__device__ float g_u_part[2][BATCH * RANK];
__device__ unsigned int g_bar;   // monotone ticket counter, never reset (replay-safe)

typedef unsigned long long ull;

__device__ __forceinline__ void ffma2(ull& d, ull a, ull b) {
    asm("fma.rn.f32x2 %0, %1, %2, %0;" : "+l"(d) : "l"(a), "l"(b));
}
__device__ __forceinline__ void unpack2(float& lo, float& hi, ull v) {
    asm("mov.b64 {%0, %1}, %2;" : "=f"(lo), "=f"(hi) : "l"(v));
}

__device__ __forceinline__ void grid_barrier() {
    __syncthreads();
    if (threadIdx.x == 0) {
        __threadfence();
        unsigned int old = atomicAdd(&g_bar, 1u);
        unsigned int target = (old / GRID + 1u) * GRID;
        while ((int)(*(volatile unsigned int*)&g_bar - target) < 0)
            __nanosleep(32);
        __threadfence();
    }
    __syncthreads();
}

__global__ void __launch_bounds__(TPB, 2) k_fused(const float* __restrict__ input,
                                                  const float* __restrict__ hidden,
                                                  const float* __restrict__ Win,
                                                  const float* __restrict__ L,
                                                  const float* __restrict__ R,
                                                  const float* __restrict__ Wout,
                                                  float* __restrict__ nh,
                                                  float* __restrict__ out) {
    const int t = threadIdx.x;
    const int lane = t & 31, w = t >> 5;    // 16 warps

    __shared__ float red[16][16];
    __shared__ __align__(16) float comb[32][24];   // phase 2: [input(16) | u(8)]

    // ========== Phase 1: u partials; r split across thread halves =========
    {
        const int bg = blockIdx.x >> 1;          // 0..127 -> 4 batch rows
        const int half = blockIdx.x & 1;         // H-half
        const int bbase = bg * 4;
        const int rh = t >> 8;                   // 0..1 -> r in [rh*4, rh*4+4)
        const int tt = t & 255;

        float acc[16];                           // acc[bl*4 + rr]
#pragma unroll
        for (int i = 0; i < 16; i++) acc[i] = 0.0f;

#pragma unroll
        for (int it = 0; it < 4; it++) {
            const int j = half * 4096 + it * 1024 + tt * 4;
            float4 h4[4];
#pragma unroll
            for (int bl = 0; bl < 4; bl++)
                h4[bl] = *(const float4*)(hidden + (bbase + bl) * HID + j);
            float th[4][4];
#pragma unroll
            for (int bl = 0; bl < 4; bl++) {
                th[bl][0] = __tanhf(h4[bl].x);
                th[bl][1] = __tanhf(h4[bl].y);
                th[bl][2] = __tanhf(h4[bl].z);
                th[bl][3] = __tanhf(h4[bl].w);
            }
#pragma unroll
            for (int rr = 0; rr < 4; rr++) {
                float4 rv = *(const float4*)(R + (rh * 4 + rr) * HID + j);
#pragma unroll
                for (int bl = 0; bl < 4; bl++) {
                    float a = acc[bl * 4 + rr];
                    a = fmaf(th[bl][0], rv.x, a);
                    a = fmaf(th[bl][1], rv.y, a);
                    a = fmaf(th[bl][2], rv.z, a);
                    a = fmaf(th[bl][3], rv.w, a);
                    acc[bl * 4 + rr] = a;
                }
            }
        }

        // fold 16 values over lane bits 0..3 (15 SHFL), then reduce bit 4
#pragma unroll
        for (int m = 8; m >= 1; m >>= 1) {
            const bool up = (lane & m) != 0;
#pragma unroll
            for (int i = 0; i < m; i++) {
                float send = up ? acc[i] : acc[i + m];
                float got = __shfl_xor_sync(0xffffffffu, send, m);
                acc[i] = (up ? acc[i + m] : acc[i]) + got;
            }
        }
        acc[0] += __shfl_xor_sync(0xffffffffu, acc[0], 16);
        // lane L holds warp total of acc[L&15]

        if (lane < 16) red[w][lane] = acc[0];    // warps 0-7: rh=0, 8-15: rh=1
        __syncthreads();
        if (t < 32) {
            const int bl = t >> 3, r = t & 7;
            const int rh2 = r >> 2, rr = r & 3;
            float s = 0.0f;
#pragma unroll
            for (int w2 = 0; w2 < 8; w2++) s += red[rh2 * 8 + w2][bl * 4 + rr];
            g_u_part[half][(bbase + bl) * RANK + r] = s;
        }
    }

    grid_barrier();

    // ===================== Phase 2: new_h (exact fp32) ====================
    {
        const int jt = blockIdx.x & 15;          // 16 j-tiles of 512
        const int bc = blockIdx.x >> 4;          // 16 batch chunks of 32
        const int b0 = bc * 32;
        const int j = jt * 512 + t;              // one j-column per thread

        // stage [input | u] per batch row: comb[bi][0..15]=input, [16..23]=u
        for (int v = t; v < 32 * 24; v += TPB) {
            const int bi = v / 24, c = v - bi * 24;
            float val;
            if (c < NIN) {
                val = input[(b0 + bi) * NIN + c];
            } else {
                const int idx = (b0 + bi) * RANK + (c - NIN);
                val = (g_u_part[0][idx] + g_u_part[1][idx]) * (1.0f / (float)HID);
            }
            comb[bi][c] = val;
        }

        ull wj[8], lj[4];
        {
            const ull* wr = (const ull*)(Win + j * NIN);
#pragma unroll
            for (int i = 0; i < 8; i++) wj[i] = wr[i];
            const ull* lr = (const ull*)(L + j * RANK);
#pragma unroll
            for (int r = 0; r < 4; r++) lj[r] = lr[r];
        }
        __syncthreads();

#pragma unroll 4
        for (int bi = 0; bi < 32; bi++) {
            const int b = b0 + bi;

            // 6x LDS.128 broadcast: 24 floats = 12 f32x2 operand pairs
            union { float4 f4[6]; ull p[12]; } cb;
            const float4* cp = (const float4*)&comb[bi][0];
#pragma unroll
            for (int q = 0; q < 6; q++) cb.f4[q] = cp[q];

            float h = hidden[b * HID + j];

            ull acc = 0ULL;
#pragma unroll
            for (int i = 0; i < 8; i++) ffma2(acc, wj[i], cb.p[i]);
#pragma unroll
            for (int r = 0; r < 4; r++) ffma2(acc, lj[r], cb.p[8 + r]);
            float lo, hi;
            unpack2(lo, hi, acc);

            nh[b * HID + j] = fmaf(0.1f, lo + hi, 0.9f * h);
        }
    }

    grid_barrier();

    // ============ Phase 3: output (2 rows per block, full H) ==============
    {
        const int bbase = blockIdx.x * 2;

        float acc[8];
#pragma unroll
        for (int i = 0; i < 8; i++) acc[i] = 0.0f;

#pragma unroll
        for (int it = 0; it < 4; it++) {
            const int j = it * 2048 + t * 4;
            float4 x0 = *(const float4*)(nh + bbase * HID + j);
            float4 x1 = *(const float4*)(nh + (bbase + 1) * HID + j);
            float th[2][4];
            th[0][0] = __tanhf(x0.x); th[0][1] = __tanhf(x0.y);
            th[0][2] = __tanhf(x0.z); th[0][3] = __tanhf(x0.w);
            th[1][0] = __tanhf(x1.x); th[1][1] = __tanhf(x1.y);
            th[1][2] = __tanhf(x1.z); th[1][3] = __tanhf(x1.w);

#pragma unroll
            for (int o = 0; o < 4; o++) {
                float4 w4 = *(const float4*)(Wout + o * HID + j);
#pragma unroll
                for (int bl = 0; bl < 2; bl++) {
                    float a = acc[bl * 4 + o];
                    a = fmaf(th[bl][0], w4.x, a);
                    a = fmaf(th[bl][1], w4.y, a);
                    a = fmaf(th[bl][2], w4.z, a);
                    a = fmaf(th[bl][3], w4.w, a);
                    acc[bl * 4 + o] = a;
                }
            }
        }

        // fold 8 values over lane bits 0..2, then reduce bits 3,4
#pragma unroll
        for (int m = 4; m >= 1; m >>= 1) {
            const bool up = (lane & m) != 0;
#pragma unroll
            for (int i = 0; i < m; i++) {
                float send = up ? acc[i] : acc[i + m];
                float got = __shfl_xor_sync(0xffffffffu, send, m);
                acc[i] = (up ? acc[i + m] : acc[i]) + got;
            }
        }
        acc[0] += __shfl_xor_sync(0xffffffffu, acc[0], 8);
        acc[0] += __shfl_xor_sync(0xffffffffu, acc[0], 16);

        __syncthreads();   // red[] reuse
        if (lane < 8) red[w][lane] = acc[0];
        __syncthreads();
        if (t < 8) {
            float s = 0.0f;
#pragma unroll
            for (int w2 = 0; w2 < 16; w2++) s += red[w2][t];
            out[(bbase + (t >> 2)) * NOUT + (t & 3)] = s * (1.0f / (float)HID);
        }
    }
}

extern "C" void kernel_launch(void* const* d_in, const int* in_sizes, int n_in,
                              void* d_out, int out_size) {
    const float* input  = (const float*)d_in[0];  // [512,16]
    const float* hidden = (const float*)d_in[1];  // [512,8192]
    const float* Win    = (const float*)d_in[2];  // [8192,16]
    const float* L      = (const float*)d_in[3];  // [8192,8]
    const float* R      = (const float*)d_in[4];  // [8,8192]
    const float* Wout   = (const float*)d_in[5];  // [4,8192]

    float* out = (float*)d_out;                   // [512,4] then [512,8192]
    float* nh  = out + BATCH * NOUT;

    k_fused<<<GRID, TPB>>>(input, hidden, Win, L, R, Wout, nh, out);
}